// round 5
// baseline (speedup 1.0000x reference)
#include <cuda_runtime.h>
#include <cstdint>

#define NN 100000
#define EE 6400000
#define PP 12
#define FF 32

#define SCAN_BLK 256
#define NBLK ((NN + SCAN_BLK - 1) / SCAN_BLK)   // 391

// scratch (device globals: no allocations allowed)
__device__ int   g_cnt[NN];          // histogram, then scatter cursor
__device__ int   g_off[NN];          // exclusive offsets (end of node n: n==NN-1 ? EE : g_off[n+1])
__device__ int   g_bsum[512];        // per-block partial sums for scan
__device__ float g_dinv[NN];
__device__ int   g_csr_src[EE];
__device__ float g_csr_w[EE];
__device__ float g_probs[PP];
__device__ float g_uz[FF], g_cz[FF], g_uh[FF], g_ch[FF];

__device__ __forceinline__ float tanh_fast(float x) {
    float r;
    asm("tanh.approx.f32 %0, %1;" : "=f"(r) : "f"(x));
    return r;
}

// ---- precompute: collapse GRU matmuls (H0==0) + softmax(attention) ----
__global__ void prep_kernel(const float* __restrict__ att,
                            const float* __restrict__ wcz, const float* __restrict__ bcz,
                            const float* __restrict__ wch, const float* __restrict__ bch,
                            const float* __restrict__ wlz, const float* __restrict__ blz,
                            const float* __restrict__ wlh, const float* __restrict__ blh) {
    int k = threadIdx.x;  // 32 threads
    float uz = 0.f, cz = blz[k], uh = 0.f, ch = blh[k];
#pragma unroll
    for (int j = 0; j < FF; j++) {
        float wz = wlz[j * FF + k], wh = wlh[j * FF + k];
        uz = fmaf(wcz[j], wz, uz);
        cz = fmaf(bcz[j], wz, cz);
        uh = fmaf(wch[j], wh, uh);
        ch = fmaf(bch[j], wh, ch);
    }
    g_uz[k] = uz; g_cz[k] = cz; g_uh[k] = uh; g_ch[k] = ch;
    if (k == 0) {
        float m = -1e30f;
        for (int p = 0; p < PP; p++) m = fmaxf(m, att[p]);
        float e[PP]; float s = 0.f;
        for (int p = 0; p < PP; p++) { e[p] = __expf(att[p] - m); s += e[p]; }
        float inv = 1.0f / s;
        for (int p = 0; p < PP; p++) g_probs[p] = e[p] * inv;
    }
}

// ---- zero histogram ----
__global__ void zero_kernel() {
    int i = blockIdx.x * blockDim.x + threadIdx.x;
    if (i < NN) g_cnt[i] = 0;
}

// ---- histogram over dst ----
__global__ void hist_kernel(const int* __restrict__ ei) {
    int e = blockIdx.x * blockDim.x + threadIdx.x;
    if (e >= EE) return;
    atomicAdd(&g_cnt[ei[EE + e]], 1);
}

// ---- scan stage 1: per-block totals ----
__global__ void scan1_kernel() {
    int i = blockIdx.x * blockDim.x + threadIdx.x;
    int v = (i < NN) ? g_cnt[i] : 0;
#pragma unroll
    for (int o = 16; o; o >>= 1) v += __shfl_xor_sync(0xffffffffu, v, o);
    __shared__ int ws[8];
    int lane = threadIdx.x & 31, wid = threadIdx.x >> 5;
    if (lane == 0) ws[wid] = v;
    __syncthreads();
    if (wid == 0) {
        int t = (lane < 8) ? ws[lane] : 0;
#pragma unroll
        for (int o = 4; o; o >>= 1) t += __shfl_xor_sync(0xffffffffu, t, o);
        if (lane == 0) g_bsum[blockIdx.x] = t;
    }
}

// ---- scan stage 2: exclusive scan of 391 block totals (1 block, 512 thr) ----
__global__ void scan2_kernel() {
    int i = threadIdx.x;  // 512 threads
    int v = (i < NBLK) ? g_bsum[i] : 0;
    int lane = i & 31, wid = i >> 5;
    int incl = v;
#pragma unroll
    for (int o = 1; o < 32; o <<= 1) {
        int t = __shfl_up_sync(0xffffffffu, incl, o);
        if (lane >= o) incl += t;
    }
    __shared__ int ws[16];
    if (lane == 31) ws[wid] = incl;
    __syncthreads();
    if (wid == 0) {
        int t = (lane < 16) ? ws[lane] : 0;
        int ti = t;
#pragma unroll
        for (int o = 1; o < 32; o <<= 1) {
            int u = __shfl_up_sync(0xffffffffu, ti, o);
            if (lane >= o) ti += u;
        }
        if (lane < 16) ws[lane] = ti - t;  // exclusive warp base
    }
    __syncthreads();
    if (i < NBLK) g_bsum[i] = incl - v + ws[wid];
}

// ---- scan stage 3: per-element exclusive offsets; init cursor ----
__global__ void scan3_kernel() {
    int i = blockIdx.x * blockDim.x + threadIdx.x;
    int v = (i < NN) ? g_cnt[i] : 0;
    int lane = threadIdx.x & 31, wid = threadIdx.x >> 5;
    int incl = v;
#pragma unroll
    for (int o = 1; o < 32; o <<= 1) {
        int t = __shfl_up_sync(0xffffffffu, incl, o);
        if (lane >= o) incl += t;
    }
    __shared__ int ws[8];
    if (lane == 31) ws[wid] = incl;
    __syncthreads();
    if (wid == 0) {
        int t = (lane < 8) ? ws[lane] : 0;
        int ti = t;
#pragma unroll
        for (int o = 1; o < 8; o <<= 1) {
            int u = __shfl_up_sync(0xffffffffu, ti, o);
            if (lane >= o) ti += u;
        }
        if (lane < 8) ws[lane] = ti - t;
    }
    __syncthreads();
    if (i < NN) {
        int off = g_bsum[blockIdx.x] + ws[wid] + incl - v;
        g_off[i] = off;
        g_cnt[i] = off;  // cursor
    }
}

// ---- scatter edges into CSR ----
__global__ void scatter_kernel(const int* __restrict__ ei,
                               const float* __restrict__ ew) {
    int e = blockIdx.x * blockDim.x + threadIdx.x;
    if (e >= EE) return;
    int s = ei[e];
    int d = ei[EE + e];
    int pos = atomicAdd(&g_cnt[d], 1);
    g_csr_src[pos] = s;
    g_csr_w[pos] = ew[e];
}

// ---- deg = segment sum of csr_w; dinv = rsqrt(deg+1). 1 warp/node ----
__global__ void deg_kernel() {
    int warp = (blockIdx.x * blockDim.x + threadIdx.x) >> 5;
    int lane = threadIdx.x & 31;
    if (warp >= NN) return;
    int beg = g_off[warp];
    int end = (warp == NN - 1) ? EE : g_off[warp + 1];
    float s = 0.f;
    for (int i = beg + lane; i < end; i += 32) s += g_csr_w[i];
#pragma unroll
    for (int o = 16; o; o >>= 1) s += __shfl_xor_sync(0xffffffffu, s, o);
    if (lane == 0) g_dinv[warp] = rsqrtf(s + 1.0f);
}

// ---- fused gather + GRU + output. 1 warp/node, lane = feature k ----
__global__ void final_kernel(const float* __restrict__ x,
                             const float* __restrict__ w_out,
                             const float* __restrict__ b_out,
                             float* __restrict__ out) {
    int warp = (blockIdx.x * blockDim.x + threadIdx.x) >> 5;
    int lane = threadIdx.x & 31;
    if (warp >= NN) return;
    int n = warp;
    int beg = g_off[n];
    int end = (n == NN - 1) ? EE : g_off[n + 1];

    float a0=0.f,a1=0.f,a2=0.f,a3=0.f,a4=0.f,a5=0.f,
          a6=0.f,a7=0.f,a8=0.f,a9=0.f,a10=0.f,a11=0.f;
    for (int i = beg + lane; i < end; i += 32) {
        int s = g_csr_src[i];
        float c = g_dinv[s] * g_csr_w[i];
        const float4* xs = (const float4*)(x + (size_t)s * PP);
        float4 v0 = xs[0], v1 = xs[1], v2 = xs[2];
        a0  = fmaf(c, v0.x, a0);  a1  = fmaf(c, v0.y, a1);
        a2  = fmaf(c, v0.z, a2);  a3  = fmaf(c, v0.w, a3);
        a4  = fmaf(c, v1.x, a4);  a5  = fmaf(c, v1.y, a5);
        a6  = fmaf(c, v1.z, a6);  a7  = fmaf(c, v1.w, a7);
        a8  = fmaf(c, v2.x, a8);  a9  = fmaf(c, v2.y, a9);
        a10 = fmaf(c, v2.z, a10); a11 = fmaf(c, v2.w, a11);
    }
#pragma unroll
    for (int o = 16; o; o >>= 1) {
        a0  += __shfl_xor_sync(0xffffffffu, a0,  o);
        a1  += __shfl_xor_sync(0xffffffffu, a1,  o);
        a2  += __shfl_xor_sync(0xffffffffu, a2,  o);
        a3  += __shfl_xor_sync(0xffffffffu, a3,  o);
        a4  += __shfl_xor_sync(0xffffffffu, a4,  o);
        a5  += __shfl_xor_sync(0xffffffffu, a5,  o);
        a6  += __shfl_xor_sync(0xffffffffu, a6,  o);
        a7  += __shfl_xor_sync(0xffffffffu, a7,  o);
        a8  += __shfl_xor_sync(0xffffffffu, a8,  o);
        a9  += __shfl_xor_sync(0xffffffffu, a9,  o);
        a10 += __shfl_xor_sync(0xffffffffu, a10, o);
        a11 += __shfl_xor_sync(0xffffffffu, a11, o);
    }
    // every lane now holds all 12 sums
    float dv = g_dinv[n];
    float dv2 = dv * dv;
    float uz = g_uz[lane], cz = g_cz[lane], uh = g_uh[lane], ch = g_ch[lane];
    const float* xn = x + (size_t)n * PP;
    float sarr[PP] = {a0,a1,a2,a3,a4,a5,a6,a7,a8,a9,a10,a11};
    float acc = 0.f;
#pragma unroll
    for (int p = 0; p < PP; p++) {
        float s = fmaf(dv, sarr[p], dv2 * __ldg(xn + p));
        float a = fmaf(s, uz, cz);
        float b = fmaf(s, uh, ch);
        // (1 - sigmoid(a)) = 0.5*(1 - tanh(a/2))
        float t1 = tanh_fast(0.5f * a);
        float t2 = tanh_fast(b);
        acc = fmaf(g_probs[p], 0.5f * (1.0f - t1) * t2, acc);
    }
    float v = fmaxf(acc, 0.0f) * w_out[lane];
#pragma unroll
    for (int o = 16; o; o >>= 1) v += __shfl_xor_sync(0xffffffffu, v, o);
    if (lane == 0) out[n] = v + b_out[0];
}

extern "C" void kernel_launch(void* const* d_in, const int* in_sizes, int n_in,
                              void* d_out, int out_size) {
    const float* x   = (const float*)d_in[0];
    const int*   ei  = (const int*)d_in[1];   // JAX w/o x64: int64 silently -> int32
    const float* ew  = (const float*)d_in[2];
    const float* att = (const float*)d_in[3];
    const float* wcz = (const float*)d_in[4];
    const float* bcz = (const float*)d_in[5];
    const float* wch = (const float*)d_in[8];
    const float* bch = (const float*)d_in[9];
    const float* wlz = (const float*)d_in[10];
    const float* blz = (const float*)d_in[11];
    const float* wlh = (const float*)d_in[14];
    const float* blh = (const float*)d_in[15];
    const float* wo  = (const float*)d_in[16];
    const float* bo  = (const float*)d_in[17];
    float*       out = (float*)d_out;

    prep_kernel<<<1, FF>>>(att, wcz, bcz, wch, bch, wlz, blz, wlh, blh);
    zero_kernel<<<NBLK, SCAN_BLK>>>();
    hist_kernel<<<(EE + 255) / 256, 256>>>(ei);
    scan1_kernel<<<NBLK, SCAN_BLK>>>();
    scan2_kernel<<<1, 512>>>();
    scan3_kernel<<<NBLK, SCAN_BLK>>>();
    scatter_kernel<<<(EE + 255) / 256, 256>>>(ei, ew);
    deg_kernel<<<(NN * 32 + 255) / 256, 256>>>();
    final_kernel<<<(NN * 32 + 255) / 256, 256>>>(x, wo, bo, out);
}

// round 6
// speedup vs baseline: 1.0538x; 1.0538x over previous
#include <cuda_runtime.h>
#include <cstdint>

#define NN 100000
#define EE 6400000
#define PP 12
#define FF 32

#define SCAN_BLK 256
#define NBLK ((NN + SCAN_BLK - 1) / SCAN_BLK)   // 391

// scratch (device globals: no allocations allowed)
__device__ int   g_cnt[NN];          // histogram, then scatter cursor
__device__ int   g_off[NN];          // exclusive offsets
__device__ int   g_bsum[512];        // per-block partial sums for scan
__device__ float g_deg[NN];
__device__ float g_dinv[NN];
__device__ unsigned long long g_csr[EE];   // packed (val<<32 | src)
__device__ float g_probs[PP];
__device__ float g_uz[FF], g_cz[FF], g_uh[FF], g_ch[FF];

__device__ __forceinline__ float tanh_fast(float x) {
    float r;
    asm("tanh.approx.f32 %0, %1;" : "=f"(r) : "f"(x));
    return r;
}

// ---- precompute: collapse GRU matmuls (H0==0) + softmax(attention) ----
__global__ void prep_kernel(const float* __restrict__ att,
                            const float* __restrict__ wcz, const float* __restrict__ bcz,
                            const float* __restrict__ wch, const float* __restrict__ bch,
                            const float* __restrict__ wlz, const float* __restrict__ blz,
                            const float* __restrict__ wlh, const float* __restrict__ blh) {
    int k = threadIdx.x;  // 32 threads
    float uz = 0.f, cz = blz[k], uh = 0.f, ch = blh[k];
#pragma unroll
    for (int j = 0; j < FF; j++) {
        float wz = wlz[j * FF + k], wh = wlh[j * FF + k];
        uz = fmaf(wcz[j], wz, uz);
        cz = fmaf(bcz[j], wz, cz);
        uh = fmaf(wch[j], wh, uh);
        ch = fmaf(bch[j], wh, ch);
    }
    g_uz[k] = uz; g_cz[k] = cz; g_uh[k] = uh; g_ch[k] = ch;
    if (k == 0) {
        float m = -1e30f;
        for (int p = 0; p < PP; p++) m = fmaxf(m, att[p]);
        float e[PP]; float s = 0.f;
        for (int p = 0; p < PP; p++) { e[p] = __expf(att[p] - m); s += e[p]; }
        float inv = 1.0f / s;
        for (int p = 0; p < PP; p++) g_probs[p] = e[p] * inv;
    }
}

// ---- zero histogram + deg ----
__global__ void zero_kernel() {
    int i = blockIdx.x * blockDim.x + threadIdx.x;
    if (i < NN) { g_cnt[i] = 0; g_deg[i] = 0.f; }
}

// ---- fused: cnt[dst]++ ; deg[dst] += w ----
__global__ void histdeg_kernel(const int* __restrict__ ei,
                               const float* __restrict__ ew) {
    int e = blockIdx.x * blockDim.x + threadIdx.x;
    if (e >= EE) return;
    int d = ei[EE + e];
    atomicAdd(&g_cnt[d], 1);
    atomicAdd(&g_deg[d], ew[e]);
}

// ---- scan stage 1: per-block totals ----
__global__ void scan1_kernel() {
    int i = blockIdx.x * blockDim.x + threadIdx.x;
    int v = (i < NN) ? g_cnt[i] : 0;
#pragma unroll
    for (int o = 16; o; o >>= 1) v += __shfl_xor_sync(0xffffffffu, v, o);
    __shared__ int ws[8];
    int lane = threadIdx.x & 31, wid = threadIdx.x >> 5;
    if (lane == 0) ws[wid] = v;
    __syncthreads();
    if (wid == 0) {
        int t = (lane < 8) ? ws[lane] : 0;
#pragma unroll
        for (int o = 4; o; o >>= 1) t += __shfl_xor_sync(0xffffffffu, t, o);
        if (lane == 0) g_bsum[blockIdx.x] = t;
    }
}

// ---- scan stage 2: exclusive scan of 391 block totals (1 block, 512 thr) ----
__global__ void scan2_kernel() {
    int i = threadIdx.x;  // 512 threads
    int v = (i < NBLK) ? g_bsum[i] : 0;
    int lane = i & 31, wid = i >> 5;
    int incl = v;
#pragma unroll
    for (int o = 1; o < 32; o <<= 1) {
        int t = __shfl_up_sync(0xffffffffu, incl, o);
        if (lane >= o) incl += t;
    }
    __shared__ int ws[16];
    if (lane == 31) ws[wid] = incl;
    __syncthreads();
    if (wid == 0) {
        int t = (lane < 16) ? ws[lane] : 0;
        int ti = t;
#pragma unroll
        for (int o = 1; o < 32; o <<= 1) {
            int u = __shfl_up_sync(0xffffffffu, ti, o);
            if (lane >= o) ti += u;
        }
        if (lane < 16) ws[lane] = ti - t;  // exclusive warp base
    }
    __syncthreads();
    if (i < NBLK) g_bsum[i] = incl - v + ws[wid];
}

// ---- scan stage 3: exclusive offsets + cursor init + dinv ----
__global__ void scan3_kernel() {
    int i = blockIdx.x * blockDim.x + threadIdx.x;
    int v = (i < NN) ? g_cnt[i] : 0;
    int lane = threadIdx.x & 31, wid = threadIdx.x >> 5;
    int incl = v;
#pragma unroll
    for (int o = 1; o < 32; o <<= 1) {
        int t = __shfl_up_sync(0xffffffffu, incl, o);
        if (lane >= o) incl += t;
    }
    __shared__ int ws[8];
    if (lane == 31) ws[wid] = incl;
    __syncthreads();
    if (wid == 0) {
        int t = (lane < 8) ? ws[lane] : 0;
        int ti = t;
#pragma unroll
        for (int o = 1; o < 8; o <<= 1) {
            int u = __shfl_up_sync(0xffffffffu, ti, o);
            if (lane >= o) ti += u;
        }
        if (lane < 8) ws[lane] = ti - t;
    }
    __syncthreads();
    if (i < NN) {
        int off = g_bsum[blockIdx.x] + ws[wid] + incl - v;
        g_off[i] = off;
        g_cnt[i] = off;                       // cursor
        g_dinv[i] = rsqrtf(g_deg[i] + 1.0f);  // fused dinv
    }
}

// ---- scatter edges into CSR: packed (dinv[src]*w, src) in one STG.64 ----
__global__ void scatter_kernel(const int* __restrict__ ei,
                               const float* __restrict__ ew) {
    int e = blockIdx.x * blockDim.x + threadIdx.x;
    if (e >= EE) return;
    int s = ei[e];
    int d = ei[EE + e];
    float val = g_dinv[s] * ew[e];
    int pos = atomicAdd(&g_cnt[d], 1);
    unsigned long long pk = ((unsigned long long)__float_as_uint(val) << 32)
                          | (unsigned int)s;
    g_csr[pos] = pk;
}

// ---- fused gather + GRU + output. 1 warp/node, lane = feature k ----
__global__ void final_kernel(const float* __restrict__ x,
                             const float* __restrict__ w_out,
                             const float* __restrict__ b_out,
                             float* __restrict__ out) {
    int warp = (blockIdx.x * blockDim.x + threadIdx.x) >> 5;
    int lane = threadIdx.x & 31;
    if (warp >= NN) return;
    int n = warp;
    int beg = g_off[n];
    int end = (n == NN - 1) ? EE : g_off[n + 1];

    float a0=0.f,a1=0.f,a2=0.f,a3=0.f,a4=0.f,a5=0.f,
          a6=0.f,a7=0.f,a8=0.f,a9=0.f,a10=0.f,a11=0.f;
    for (int i = beg + lane; i < end; i += 32) {
        unsigned long long pk = g_csr[i];
        int s = (int)(pk & 0xffffffffu);
        float c = __uint_as_float((unsigned int)(pk >> 32));
        const float4* xs = (const float4*)(x + (size_t)s * PP);
        float4 v0 = xs[0], v1 = xs[1], v2 = xs[2];
        a0  = fmaf(c, v0.x, a0);  a1  = fmaf(c, v0.y, a1);
        a2  = fmaf(c, v0.z, a2);  a3  = fmaf(c, v0.w, a3);
        a4  = fmaf(c, v1.x, a4);  a5  = fmaf(c, v1.y, a5);
        a6  = fmaf(c, v1.z, a6);  a7  = fmaf(c, v1.w, a7);
        a8  = fmaf(c, v2.x, a8);  a9  = fmaf(c, v2.y, a9);
        a10 = fmaf(c, v2.z, a10); a11 = fmaf(c, v2.w, a11);
    }
#pragma unroll
    for (int o = 16; o; o >>= 1) {
        a0  += __shfl_xor_sync(0xffffffffu, a0,  o);
        a1  += __shfl_xor_sync(0xffffffffu, a1,  o);
        a2  += __shfl_xor_sync(0xffffffffu, a2,  o);
        a3  += __shfl_xor_sync(0xffffffffu, a3,  o);
        a4  += __shfl_xor_sync(0xffffffffu, a4,  o);
        a5  += __shfl_xor_sync(0xffffffffu, a5,  o);
        a6  += __shfl_xor_sync(0xffffffffu, a6,  o);
        a7  += __shfl_xor_sync(0xffffffffu, a7,  o);
        a8  += __shfl_xor_sync(0xffffffffu, a8,  o);
        a9  += __shfl_xor_sync(0xffffffffu, a9,  o);
        a10 += __shfl_xor_sync(0xffffffffu, a10, o);
        a11 += __shfl_xor_sync(0xffffffffu, a11, o);
    }
    // every lane now holds all 12 sums (= Σ dinv_s*w*x_s ; scale by dinv_d below)
    float dv = g_dinv[n];
    float dv2 = dv * dv;
    float uz = g_uz[lane], cz = g_cz[lane], uh = g_uh[lane], ch = g_ch[lane];
    const float* xn = x + (size_t)n * PP;
    float sarr[PP] = {a0,a1,a2,a3,a4,a5,a6,a7,a8,a9,a10,a11};
    float acc = 0.f;
#pragma unroll
    for (int p = 0; p < PP; p++) {
        float s = fmaf(dv, sarr[p], dv2 * __ldg(xn + p));
        float a = fmaf(s, uz, cz);
        float b = fmaf(s, uh, ch);
        // (1 - sigmoid(a)) = 0.5*(1 - tanh(a/2))
        float t1 = tanh_fast(0.5f * a);
        float t2 = tanh_fast(b);
        acc = fmaf(g_probs[p], 0.5f * (1.0f - t1) * t2, acc);
    }
    float v = fmaxf(acc, 0.0f) * w_out[lane];
#pragma unroll
    for (int o = 16; o; o >>= 1) v += __shfl_xor_sync(0xffffffffu, v, o);
    if (lane == 0) out[n] = v + b_out[0];
}

extern "C" void kernel_launch(void* const* d_in, const int* in_sizes, int n_in,
                              void* d_out, int out_size) {
    const float* x   = (const float*)d_in[0];
    const int*   ei  = (const int*)d_in[1];   // JAX w/o x64: int64 silently -> int32
    const float* ew  = (const float*)d_in[2];
    const float* att = (const float*)d_in[3];
    const float* wcz = (const float*)d_in[4];
    const float* bcz = (const float*)d_in[5];
    const float* wch = (const float*)d_in[8];
    const float* bch = (const float*)d_in[9];
    const float* wlz = (const float*)d_in[10];
    const float* blz = (const float*)d_in[11];
    const float* wlh = (const float*)d_in[14];
    const float* blh = (const float*)d_in[15];
    const float* wo  = (const float*)d_in[16];
    const float* bo  = (const float*)d_in[17];
    float*       out = (float*)d_out;

    prep_kernel<<<1, FF>>>(att, wcz, bcz, wch, bch, wlz, blz, wlh, blh);
    zero_kernel<<<NBLK, SCAN_BLK>>>();
    histdeg_kernel<<<(EE + 255) / 256, 256>>>(ei, ew);
    scan1_kernel<<<NBLK, SCAN_BLK>>>();
    scan2_kernel<<<1, 512>>>();
    scan3_kernel<<<NBLK, SCAN_BLK>>>();
    scatter_kernel<<<(EE + 255) / 256, 256>>>(ei, ew);
    final_kernel<<<(NN * 32 + 255) / 256, 256>>>(x, wo, bo, out);
}